// round 16
// baseline (speedup 1.0000x reference)
#include <cuda_runtime.h>
#include <cuda_bf16.h>
#include <math.h>
#include <stdint.h>

#define C 512
#define HWN 1024
#define CHW (C*HWN)

__device__ __align__(16) float d_G[1024];        // G[i*32+x]
__device__ float d_mean[C];
__device__ float d_scale[C];
__device__ unsigned g_tick;                      // monotonic election ticket
__device__ __align__(16) float d_out32T[CHW];    // [hw][c]
__device__ __align__(16) float d_sigT[CHW];      // [hw][c]
__device__ __align__(16) float d_tmpT[CHW];      // [(i*32+y)][c]
__device__ __align__(16) float d_ps[4*1024*9];   // per-ctile partial scores
__device__ __align__(16) __nv_bfloat16 d_wh[CHW], d_wl[CHW];          // W split
__device__ __align__(16) __nv_bfloat16 d_cath[2*CHW], d_catl[2*CHW];  // cat split
__device__ __align__(16) float d_y[4*CHW];       // 4 k-split partials

__device__ __forceinline__ float tanhapx(float x) {
    float y; asm("tanh.approx.f32 %0, %1;" : "=f"(y) : "f"(x)); return y;
}
__device__ __forceinline__ float sig1(float v) {
    return fmaf(tanhapx(0.5f * v), 0.5f, 0.5f);
}
__device__ __forceinline__ uint32_t pack_bf2(float a, float b) {
    __nv_bfloat162 t(__float2bfloat16_rn(a), __float2bfloat16_rn(b));
    return *reinterpret_cast<uint32_t*>(&t);
}
__device__ __forceinline__ void split4(const float4& v, uint2& hi, uint2& lo) {
    float h0 = __bfloat162float(__float2bfloat16_rn(v.x));
    float h1 = __bfloat162float(__float2bfloat16_rn(v.y));
    float h2 = __bfloat162float(__float2bfloat16_rn(v.z));
    float h3 = __bfloat162float(__float2bfloat16_rn(v.w));
    hi = make_uint2(pack_bf2(h0, h1), pack_bf2(h2, h3));
    lo = make_uint2(pack_bf2(v.x - h0, v.y - h1), pack_bf2(v.z - h2, v.w - h3));
}

// ---- blocks 0..511: means + W split (+ elected SE); block 512: gaussian ----
__global__ void k_init(const float* __restrict__ x, const float* __restrict__ wd,
                       const float* __restrict__ w1, const float* __restrict__ w2) {
    int t = threadIdx.x;
    if (blockIdx.x == 512) {
        int i = t;
        if (i < 32) {
            float ev[32]; float s = 0.f;
            #pragma unroll
            for (int xx = 0; xx < 32; xx++) {
                float dd = (float)(xx - i);
                float e = expf(-dd * dd * (1.0f/4.5f));
                ev[xx] = e; s += e;
            }
            float inv = 1.f / s;
            #pragma unroll
            for (int xx = 0; xx < 32; xx++) d_G[i*32 + xx] = ev[xx] * inv;
        }
        return;
    }
    int c = blockIdx.x;
    float4 wv = *reinterpret_cast<const float4*>(wd + (size_t)c*1024 + t*4);
    uint2 hi, lo; split4(wv, hi, lo);
    *reinterpret_cast<uint2*>(&d_wh[(size_t)c*1024 + t*4]) = hi;
    *reinterpret_cast<uint2*>(&d_wl[(size_t)c*1024 + t*4]) = lo;
    float4 v = reinterpret_cast<const float4*>(x + c*HWN)[t];
    float s = v.x + v.y + v.z + v.w;
    #pragma unroll
    for (int o = 16; o > 0; o >>= 1) s += __shfl_xor_sync(~0u, s, o);
    __shared__ float red[8];
    __shared__ int elected;
    if ((t & 31) == 0) red[t >> 5] = s;
    __syncthreads();
    if (t == 0) {
        float tot = 0.f;
        #pragma unroll
        for (int w = 0; w < 8; w++) tot += red[w];
        d_mean[c] = tot * (1.f/1024.f);
        __threadfence();
        unsigned old = atomicAdd(&g_tick, 1u);
        elected = ((old & 511u) == 511u);
    }
    __syncthreads();
    if (!elected) return;
    // ---- last block: SE (means -> scale) ----
    __threadfence();   // acquire: all means visible
    __shared__ float sM[512], s1[32];
    sM[t] = d_mean[t]; sM[t + 256] = d_mean[t + 256];
    __syncthreads();
    int o = t >> 3, l = t & 7;       // 32 outputs x 8 lanes
    float a = 0.f;
    #pragma unroll
    for (int j = 0; j < 16; j++) {
        int cc = (l + j*8) * 4;
        float4 w = *reinterpret_cast<const float4*>(w1 + o*512 + cc);
        a += w.x*sM[cc] + w.y*sM[cc+1] + w.z*sM[cc+2] + w.w*sM[cc+3];
    }
    #pragma unroll
    for (int off = 4; off > 0; off >>= 1) a += __shfl_down_sync(~0u, a, off, 8);
    if (l == 0) s1[o] = fmaxf(a, 0.f);
    __syncthreads();
    #pragma unroll
    for (int k = 0; k < 2; k++) {
        int oo = t + k*256;
        float b = 0.f;
        const float4* w2p = reinterpret_cast<const float4*>(w2 + oo*32);
        #pragma unroll
        for (int j = 0; j < 8; j++) {
            float4 w = w2p[j];
            b += w.x*s1[j*4+0] + w.y*s1[j*4+1] + w.z*s1[j*4+2] + w.w*s1[j*4+3];
        }
        d_scale[oo] = 1.f / (1.f + expf(-b));
    }
}

// ---- scale + sigmoid + transpose ----
__global__ void k_trans(const float* __restrict__ x) {
    int p0 = blockIdx.x * 32;
    int c0 = blockIdx.y * 32;
    int t = threadIdx.x;
    __shared__ float V[32][33], S[32][33];
    int r = t >> 3, q = (t & 7) * 4;
    float4 xv = *reinterpret_cast<const float4*>(x + (c0 + r)*HWN + p0 + q);
    float sc = d_scale[c0 + r];
    float4 v; v.x = xv.x*sc; v.y = xv.y*sc; v.z = xv.z*sc; v.w = xv.w*sc;
    V[r][q+0] = v.x; V[r][q+1] = v.y; V[r][q+2] = v.z; V[r][q+3] = v.w;
    S[r][q+0] = sig1(v.x);
    S[r][q+1] = sig1(v.y);
    S[r][q+2] = sig1(v.z);
    S[r][q+3] = sig1(v.w);
    __syncthreads();
    int pr = t >> 3, cq = (t & 7) * 4;
    float4 ov, sv;
    ov.x = V[cq+0][pr]; ov.y = V[cq+1][pr]; ov.z = V[cq+2][pr]; ov.w = V[cq+3][pr];
    sv.x = S[cq+0][pr]; sv.y = S[cq+1][pr]; sv.z = S[cq+2][pr]; sv.w = S[cq+3][pr];
    *reinterpret_cast<float4*>(d_out32T + (p0 + pr)*512 + c0 + cq) = ov;
    *reinterpret_cast<float4*>(d_sigT   + (p0 + pr)*512 + c0 + cq) = sv;
}

// ---- P1: blocks 0..63 gauss stage1 (256ch, 8 rows/thread); 64..191 CSA score ----
__global__ void __launch_bounds__(256) k_p1() {
    __shared__ float SM[12288];   // 48KB
    int t = threadIdx.x, bid = blockIdx.x;
    if (bid < 64) {
        float* sG = SM;            // [1024]
        float* sm = SM + 1024;     // [32 x][256 c]
        #pragma unroll
        for (int j = 0; j < 4; j++) sG[t + j*256] = d_G[t + j*256];
        int c0 = (bid & 1) * 256;
        int rs = bid >> 1;   // y
        #pragma unroll
        for (int j = 0; j < 8; j++) {
            int idx = t + j*256;
            int rr = idx >> 6, cq = (idx & 63) * 4;
            *reinterpret_cast<float4*>(&sm[rr*256 + cq]) =
                *reinterpret_cast<const float4*>(d_out32T + (size_t)(rr*32 + rs)*512 + c0 + cq);
        }
        __syncthreads();
        int g = t >> 6, c4 = (t & 63) * 4;
        float4 acc[8];
        #pragma unroll
        for (int u = 0; u < 8; u++) acc[u] = make_float4(0.f, 0.f, 0.f, 0.f);
        #pragma unroll
        for (int xx = 0; xx < 32; xx += 4) {
            float4 sv0 = *reinterpret_cast<const float4*>(&sm[(xx+0)*256 + c4]);
            float4 sv1 = *reinterpret_cast<const float4*>(&sm[(xx+1)*256 + c4]);
            float4 sv2 = *reinterpret_cast<const float4*>(&sm[(xx+2)*256 + c4]);
            float4 sv3 = *reinterpret_cast<const float4*>(&sm[(xx+3)*256 + c4]);
            #pragma unroll
            for (int ii = 0; ii < 8; ii++) {
                float4 gg = *reinterpret_cast<const float4*>(&sG[(g*8+ii)*32 + xx]);
                acc[ii].x += gg.x*sv0.x + gg.y*sv1.x + gg.z*sv2.x + gg.w*sv3.x;
                acc[ii].y += gg.x*sv0.y + gg.y*sv1.y + gg.z*sv2.y + gg.w*sv3.y;
                acc[ii].z += gg.x*sv0.z + gg.y*sv1.z + gg.z*sv2.z + gg.w*sv3.z;
                acc[ii].w += gg.x*sv0.w + gg.y*sv1.w + gg.z*sv2.w + gg.w*sv3.w;
            }
        }
        #pragma unroll
        for (int ii = 0; ii < 8; ii++) {
            int i = g*8 + ii;
            *reinterpret_cast<float4*>(d_tmpT + (size_t)(i*32 + rs)*512 + c0 + c4) = acc[ii];
        }
    } else {
        int b = bid - 64, h = b >> 2, ct = b & 3;
        #pragma unroll
        for (int j = 0; j < 12; j++) {
            int idx = t + j*256;
            int r = idx >> 10, rem = idx & 1023;
            int w = rem >> 5, c4 = (rem & 31) * 4;
            int gh = h - 1 + r;
            float4 v = make_float4(0.f, 0.f, 0.f, 0.f);
            if (gh >= 0 && gh < 32)
                v = *reinterpret_cast<const float4*>(d_sigT + (size_t)(gh*32 + w)*512 + ct*128 + c4);
            *reinterpret_cast<float4*>(&SM[idx*4]) = v;   // r*4096 + w*128 + c4
        }
        __syncthreads();
        int warp = t >> 5, lane = t & 31, c4 = lane*4;
        #pragma unroll
        for (int wp = 0; wp < 4; wp++) {
            int w = wp*8 + warp;
            float4 cen = *reinterpret_cast<const float4*>(&SM[4096 + w*128 + c4]);
            float part[9];
            #pragma unroll
            for (int di = 0; di < 3; di++) {
                #pragma unroll
                for (int dj = 0; dj < 3; dj++) {
                    int d = di*3 + dj;
                    int gw = w + dj - 1;
                    int gwc = min(max(gw, 0), 31);
                    float s = (gw == gwc) ? 1.f : 0.f;
                    const float4 nb = *reinterpret_cast<const float4*>(&SM[di*4096 + gwc*128 + c4]);
                    part[d] = s * (cen.x*nb.x + cen.y*nb.y + cen.z*nb.z + cen.w*nb.w);
                }
            }
            #pragma unroll
            for (int d = 0; d < 9; d++) {
                float v = part[d];
                #pragma unroll
                for (int o = 16; o > 0; o >>= 1) v += __shfl_xor_sync(~0u, v, o);
                if (lane == 0) d_ps[ct*9216 + h*288 + w*9 + d] = v;
            }
        }
    }
}

// ---- P2: blocks 0..63 gauss stage2 (256ch, bf16 out); 64..191 CSA apply ----
__global__ void __launch_bounds__(256) k_p2() {
    __shared__ float SM[12288];
    int t = threadIdx.x, bid = blockIdx.x;
    if (bid < 64) {
        float* sG = SM;
        float* sm = SM + 1024;     // [32 y][256 c]
        #pragma unroll
        for (int j = 0; j < 4; j++) sG[t + j*256] = d_G[t + j*256];
        int c0 = (bid & 1) * 256;
        int rs = bid >> 1;   // i
        #pragma unroll
        for (int j = 0; j < 8; j++) {
            int idx = t + j*256;
            int rr = idx >> 6, cq = (idx & 63) * 4;
            *reinterpret_cast<float4*>(&sm[rr*256 + cq]) =
                *reinterpret_cast<const float4*>(d_tmpT + (size_t)(rs*32 + rr)*512 + c0 + cq);
        }
        __syncthreads();
        int g = t >> 6, c4 = (t & 63) * 4;
        float4 acc[8];
        #pragma unroll
        for (int u = 0; u < 8; u++) acc[u] = make_float4(0.f, 0.f, 0.f, 0.f);
        #pragma unroll
        for (int y = 0; y < 32; y += 4) {
            float4 sv0 = *reinterpret_cast<const float4*>(&sm[(y+0)*256 + c4]);
            float4 sv1 = *reinterpret_cast<const float4*>(&sm[(y+1)*256 + c4]);
            float4 sv2 = *reinterpret_cast<const float4*>(&sm[(y+2)*256 + c4]);
            float4 sv3 = *reinterpret_cast<const float4*>(&sm[(y+3)*256 + c4]);
            #pragma unroll
            for (int ii = 0; ii < 8; ii++) {
                float4 gg = *reinterpret_cast<const float4*>(&sG[(g*8+ii)*32 + y]);
                acc[ii].x += gg.x*sv0.x + gg.y*sv1.x + gg.z*sv2.x + gg.w*sv3.x;
                acc[ii].y += gg.x*sv0.y + gg.y*sv1.y + gg.z*sv2.y + gg.w*sv3.y;
                acc[ii].z += gg.x*sv0.z + gg.y*sv1.z + gg.z*sv2.z + gg.w*sv3.z;
                acc[ii].w += gg.x*sv0.w + gg.y*sv1.w + gg.z*sv2.w + gg.w*sv3.w;
            }
        }
        #pragma unroll
        for (int ii = 0; ii < 8; ii++) {
            int k = g*8 + ii;
            size_t f = (size_t)(rs*32 + k)*512 + c0 + c4;
            uint2 hi, lo; split4(acc[ii], hi, lo);
            *reinterpret_cast<uint2*>(&d_cath[f]) = hi;
            *reinterpret_cast<uint2*>(&d_catl[f]) = lo;
        }
    } else {
        int b = bid - 64, h = b >> 2, ct = b & 3;
        int warp = t >> 5, lane = t & 31, c4 = lane*4;
        #pragma unroll
        for (int j = 0; j < 12; j++) {
            int idx = t + j*256;
            int r = idx >> 10, rem = idx & 1023;
            int w = rem >> 5, cq = (rem & 31) * 4;
            int gh = h - 1 + r;
            float4 v = make_float4(0.f, 0.f, 0.f, 0.f);
            if (gh >= 0 && gh < 32)
                v = *reinterpret_cast<const float4*>(d_out32T + (size_t)(gh*32 + w)*512 + ct*128 + cq);
            *reinterpret_cast<float4*>(&SM[idx*4]) = v;
        }
        float a[9];
        #pragma unroll
        for (int d = 0; d < 9; d++) a[d] = 0.f;
        if (lane < 4) {
            int w = lane*8 + warp;
            float s[9];
            #pragma unroll
            for (int d = 0; d < 9; d++)
                s[d] = (d_ps[0*9216 + h*288 + w*9 + d] + d_ps[1*9216 + h*288 + w*9 + d]
                      + d_ps[2*9216 + h*288 + w*9 + d] + d_ps[3*9216 + h*288 + w*9 + d])
                      * (1.f/512.f);
            float m = s[0];
            #pragma unroll
            for (int d = 1; d < 9; d++) m = fmaxf(m, s[d]);
            float ss = 0.f;
            #pragma unroll
            for (int d = 0; d < 9; d++) { a[d] = expf(s[d] - m); ss += a[d]; }
            float inv = 1.f / ss;
            #pragma unroll
            for (int d = 0; d < 9; d++) a[d] *= inv;
        }
        __syncthreads();
        #pragma unroll
        for (int wp = 0; wp < 4; wp++) {
            int w = wp*8 + warp;
            float at[9];
            #pragma unroll
            for (int d = 0; d < 9; d++) at[d] = __shfl_sync(~0u, a[d], wp);
            float4 acc = make_float4(0.f, 0.f, 0.f, 0.f);
            #pragma unroll
            for (int di = 0; di < 3; di++) {
                #pragma unroll
                for (int dj = 0; dj < 3; dj++) {
                    int gw = w + dj - 1;
                    int gwc = min(max(gw, 0), 31);
                    float s = (gw == gwc) ? 1.f : 0.f;
                    const float4 nb = *reinterpret_cast<const float4*>(&SM[di*4096 + gwc*128 + c4]);
                    float av = at[di*3 + dj] * s;
                    acc.x += av*nb.x; acc.y += av*nb.y; acc.z += av*nb.z; acc.w += av*nb.w;
                }
            }
            size_t f = (size_t)CHW + (size_t)(h*32 + w)*512 + ct*128 + c4;
            uint2 hi, lo; split4(acc, hi, lo);
            *reinterpret_cast<uint2*>(&d_cath[f]) = hi;
            *reinterpret_cast<uint2*>(&d_catl[f]) = lo;
        }
    }
}

// ==================== mma.sync bf16 GEMM with preconverted operands ====
#define SMA_PITCH 80
#define SMB_PITCH 272
#define OFF_AL 10240
#define OFF_BH 20480
#define OFF_BL 29184

#define LDM_X4(r0,r1,r2,r3,addr) \
  asm volatile("ldmatrix.sync.aligned.m8n8.x4.shared.b16 {%0,%1,%2,%3},[%4];" \
    : "=r"(r0),"=r"(r1),"=r"(r2),"=r"(r3) : "r"(addr))
#define LDM_X4T(r0,r1,r2,r3,addr) \
  asm volatile("ldmatrix.sync.aligned.m8n8.x4.trans.shared.b16 {%0,%1,%2,%3},[%4];" \
    : "=r"(r0),"=r"(r1),"=r"(r2),"=r"(r3) : "r"(addr))
#define MMA(d,a,b0,b1) \
  asm volatile("mma.sync.aligned.m16n8k16.row.col.f32.bf16.bf16.f32 " \
    "{%0,%1,%2,%3},{%4,%5,%6,%7},{%8,%9},{%0,%1,%2,%3};" \
    : "+f"(d[0]),"+f"(d[1]),"+f"(d[2]),"+f"(d[3]) \
    : "r"(a[0]),"r"(a[1]),"r"(a[2]),"r"(a[3]),"r"(b0),"r"(b1))

__device__ __forceinline__ uint32_t smem_u32(const void* p) {
    uint32_t a;
    asm("{ .reg .u64 t; cvta.to.shared.u64 t, %1; cvt.u32.u64 %0, t; }" : "=r"(a) : "l"(p));
    return a;
}

__global__ void __launch_bounds__(256) k_gemm_mma() {
    __shared__ __align__(16) char sm[37888];
    uint32_t sb = smem_u32(sm);
    int t = threadIdx.x, wid = t >> 5, lane = t & 31;
    int n0 = blockIdx.x * 128;
    int m0 = blockIdx.y * 128;
    int kz = blockIdx.z * 256;
    int wm = (wid & 1) * 64, wn = (wid >> 1) * 32;

    float acc[4][4][4];
    #pragma unroll
    for (int a = 0; a < 4; a++)
        #pragma unroll
        for (int b = 0; b < 4; b++)
            #pragma unroll
            for (int cxx = 0; cxx < 4; cxx++) acc[a][b][cxx] = 0.f;

    int q = lane >> 3, r = lane & 7;
    uint32_t a_lm = sb + (uint32_t)(wm + r + ((q & 1) << 3)) * SMA_PITCH + ((q >> 1) << 3) * 2;
    uint32_t b_lm = sb + OFF_BH + (uint32_t)(r + ((q & 1) << 3)) * SMB_PITCH
                  + (uint32_t)(wn + ((q >> 1) << 3)) * 2;

    int am = t >> 1, half = t & 1;
    int bk = t >> 3, bq = t & 7;
    const __nv_bfloat16* agh = d_wh + (size_t)(m0 + am)*1024 + kz + half*16;
    const __nv_bfloat16* agl = d_wl + (size_t)(m0 + am)*1024 + kz + half*16;
    const __nv_bfloat16* bgh = d_cath + (size_t)(kz + bk)*1024 + n0 + bq*16;
    const __nv_bfloat16* bgl = d_catl + (size_t)(kz + bk)*1024 + n0 + bq*16;
    char* smaA = sm + am*SMA_PITCH + half*32;
    char* smbB = sm + OFF_BH + bk*SMB_PITCH + bq*32;

    for (int kc = 0; kc < 8; kc++) {
        uint4 pah0 = *reinterpret_cast<const uint4*>(agh + kc*32);
        uint4 pah1 = *reinterpret_cast<const uint4*>(agh + kc*32 + 8);
        uint4 pal0 = *reinterpret_cast<const uint4*>(agl + kc*32);
        uint4 pal1 = *reinterpret_cast<const uint4*>(agl + kc*32 + 8);
        uint4 pbh0 = *reinterpret_cast<const uint4*>(bgh + (size_t)kc*32*1024);
        uint4 pbh1 = *reinterpret_cast<const uint4*>(bgh + (size_t)kc*32*1024 + 8);
        uint4 pbl0 = *reinterpret_cast<const uint4*>(bgl + (size_t)kc*32*1024);
        uint4 pbl1 = *reinterpret_cast<const uint4*>(bgl + (size_t)kc*32*1024 + 8);
        __syncthreads();
        *reinterpret_cast<uint4*>(smaA) = pah0;
        *reinterpret_cast<uint4*>(smaA + 16) = pah1;
        *reinterpret_cast<uint4*>(smaA + OFF_AL) = pal0;
        *reinterpret_cast<uint4*>(smaA + OFF_AL + 16) = pal1;
        *reinterpret_cast<uint4*>(smbB) = pbh0;
        *reinterpret_cast<uint4*>(smbB + 16) = pbh1;
        *reinterpret_cast<uint4*>(smbB + (OFF_BL - OFF_BH)) = pbl0;
        *reinterpret_cast<uint4*>(smbB + (OFF_BL - OFF_BH) + 16) = pbl1;
        __syncthreads();
        #pragma unroll
        for (int ks = 0; ks < 2; ks++) {
            uint32_t ah[4][4], al[4][4], bh[2][4], bl[2][4];
            #pragma unroll
            for (int mi = 0; mi < 4; mi++) {
                uint32_t ad = a_lm + mi*16*SMA_PITCH + ks*32;
                LDM_X4(ah[mi][0], ah[mi][1], ah[mi][2], ah[mi][3], ad);
                LDM_X4(al[mi][0], al[mi][1], al[mi][2], al[mi][3], ad + OFF_AL);
            }
            #pragma unroll
            for (int nj = 0; nj < 2; nj++) {
                uint32_t bd = b_lm + nj*32 + ks*16*SMB_PITCH;
                LDM_X4T(bh[nj][0], bh[nj][1], bh[nj][2], bh[nj][3], bd);
                LDM_X4T(bl[nj][0], bl[nj][1], bl[nj][2], bl[nj][3], bd + (OFF_BL - OFF_BH));
            }
            #pragma unroll
            for (int mi = 0; mi < 4; mi++) {
                #pragma unroll
                for (int nj = 0; nj < 2; nj++) {
                    MMA(acc[mi][2*nj],   ah[mi], bh[nj][0], bh[nj][1]);
                    MMA(acc[mi][2*nj],   ah[mi], bl[nj][0], bl[nj][1]);
                    MMA(acc[mi][2*nj],   al[mi], bh[nj][0], bh[nj][1]);
                    MMA(acc[mi][2*nj+1], ah[mi], bh[nj][2], bh[nj][3]);
                    MMA(acc[mi][2*nj+1], ah[mi], bl[nj][2], bl[nj][3]);
                    MMA(acc[mi][2*nj+1], al[mi], bh[nj][2], bh[nj][3]);
                }
            }
        }
    }
    int g = lane >> 2, tq = lane & 3;
    float* base = d_y + (size_t)blockIdx.z * CHW;
    #pragma unroll
    for (int mi = 0; mi < 4; mi++) {
        int row = m0 + wm + mi*16 + g;
        #pragma unroll
        for (int ni = 0; ni < 4; ni++) {
            int col = n0 + wn + ni*8 + tq*2;
            *reinterpret_cast<float2*>(base + (size_t)row*1024 + col) =
                make_float2(acc[mi][ni][0], acc[mi][ni][1]);
            *reinterpret_cast<float2*>(base + (size_t)(row+8)*1024 + col) =
                make_float2(acc[mi][ni][2], acc[mi][ni][3]);
        }
    }
}

// ---- instance norm (+ k-split reduce) + leaky relu(0.2) ----
__global__ void k_inorm(float* __restrict__ out) {
    int o = blockIdx.x, t = threadIdx.x;
    __shared__ float red[8];
    __shared__ float bmu, brs;
    float4 v0 = reinterpret_cast<const float4*>(d_y + 0*CHW + o*1024)[t];
    float4 v1 = reinterpret_cast<const float4*>(d_y + 1*CHW + o*1024)[t];
    float4 v2 = reinterpret_cast<const float4*>(d_y + 2*CHW + o*1024)[t];
    float4 v3 = reinterpret_cast<const float4*>(d_y + 3*CHW + o*1024)[t];
    float4 v;
    v.x = (v0.x + v1.x) + (v2.x + v3.x);
    v.y = (v0.y + v1.y) + (v2.y + v3.y);
    v.z = (v0.z + v1.z) + (v2.z + v3.z);
    v.w = (v0.w + v1.w) + (v2.w + v3.w);
    float s = v.x + v.y + v.z + v.w;
    #pragma unroll
    for (int off = 16; off > 0; off >>= 1) s += __shfl_xor_sync(~0u, s, off);
    if ((t & 31) == 0) red[t >> 5] = s;
    __syncthreads();
    if (t == 0) {
        float tot = 0.f;
        #pragma unroll
        for (int w = 0; w < 8; w++) tot += red[w];
        bmu = tot * (1.f/1024.f);
    }
    __syncthreads();
    float mu = bmu;
    float dx = v.x - mu, dy = v.y - mu, dz = v.z - mu, dw = v.w - mu;
    float qq = dx*dx + dy*dy + dz*dz + dw*dw;
    #pragma unroll
    for (int off = 16; off > 0; off >>= 1) qq += __shfl_xor_sync(~0u, qq, off);
    if ((t & 31) == 0) red[t >> 5] = qq;
    __syncthreads();
    if (t == 0) {
        float tot = 0.f;
        #pragma unroll
        for (int w = 0; w < 8; w++) tot += red[w];
        brs = rsqrtf(tot * (1.f/1024.f) + 1e-5f);
    }
    __syncthreads();
    float rs = brs;
    float4 rr;
    rr.x = dx*rs; rr.y = dy*rs; rr.z = dz*rs; rr.w = dw*rs;
    rr.x = rr.x >= 0.f ? rr.x : 0.2f*rr.x;
    rr.y = rr.y >= 0.f ? rr.y : 0.2f*rr.y;
    rr.z = rr.z >= 0.f ? rr.z : 0.2f*rr.z;
    rr.w = rr.w >= 0.f ? rr.w : 0.2f*rr.w;
    reinterpret_cast<float4*>(out + o*1024)[t] = rr;
}

extern "C" void kernel_launch(void* const* d_in, const int* in_sizes, int n_in,
                              void* d_out, int out_size) {
    const float* x  = (const float*)d_in[0];
    const float* w1 = (const float*)d_in[1];
    const float* w2 = (const float*)d_in[2];
    const float* wd = (const float*)d_in[3];
    float* out = (float*)d_out;

    k_init<<<513, 256>>>(x, wd, w1, w2);
    k_trans<<<dim3(32, 16), 256>>>(x);
    k_p1<<<192, 256>>>();
    k_p2<<<192, 256>>>();
    k_gemm_mma<<<dim3(8, 4, 4), 256>>>();
    k_inorm<<<512, 256>>>(out);
}

// round 17
// speedup vs baseline: 1.1021x; 1.1021x over previous
#include <cuda_runtime.h>
#include <cuda_bf16.h>
#include <math.h>
#include <stdint.h>

#define C 512
#define HWN 1024
#define CHW (C*HWN)

#define GDC_WAIT() asm volatile("griddepcontrol.wait;" ::: "memory")

__device__ __align__(16) float d_G[1024];        // G[i*32+x]
__device__ float d_mean[C];
__device__ float d_scale[C];
__device__ __align__(16) float d_out32T[CHW];    // [hw][c]
__device__ __align__(16) float d_sigT[CHW];      // [hw][c]
__device__ __align__(16) float d_tmpT[CHW];      // [(i*32+y)][c]
__device__ __align__(16) float d_ps[4*1024*9];   // per-ctile partial scores
__device__ __align__(16) __nv_bfloat16 d_wh[CHW], d_wl[CHW];          // W split
__device__ __align__(16) __nv_bfloat16 d_cath[2*CHW], d_catl[2*CHW];  // cat split
__device__ __align__(16) float d_y[4*CHW];       // 4 k-split partials

__device__ __forceinline__ float tanhapx(float x) {
    float y; asm("tanh.approx.f32 %0, %1;" : "=f"(y) : "f"(x)); return y;
}
__device__ __forceinline__ float sig1(float v) {
    return fmaf(tanhapx(0.5f * v), 0.5f, 0.5f);
}
__device__ __forceinline__ uint32_t pack_bf2(float a, float b) {
    __nv_bfloat162 t(__float2bfloat16_rn(a), __float2bfloat16_rn(b));
    return *reinterpret_cast<uint32_t*>(&t);
}
__device__ __forceinline__ void split4(const float4& v, uint2& hi, uint2& lo) {
    float h0 = __bfloat162float(__float2bfloat16_rn(v.x));
    float h1 = __bfloat162float(__float2bfloat16_rn(v.y));
    float h2 = __bfloat162float(__float2bfloat16_rn(v.z));
    float h3 = __bfloat162float(__float2bfloat16_rn(v.w));
    hi = make_uint2(pack_bf2(h0, h1), pack_bf2(h2, h3));
    lo = make_uint2(pack_bf2(v.x - h0, v.y - h1), pack_bf2(v.z - h2, v.w - h3));
}

// ---- blocks 0..511: channel means + W bf16 split; block 512: gaussian weights ----
__global__ void k_init(const float* __restrict__ x, const float* __restrict__ wd) {
    int t = threadIdx.x;
    if (blockIdx.x == 512) {
        int i = t;
        if (i < 32) {
            float ev[32]; float s = 0.f;
            #pragma unroll
            for (int xx = 0; xx < 32; xx++) {
                float dd = (float)(xx - i);
                float e = expf(-dd * dd * (1.0f/4.5f));
                ev[xx] = e; s += e;
            }
            float inv = 1.f / s;
            #pragma unroll
            for (int xx = 0; xx < 32; xx++) d_G[i*32 + xx] = ev[xx] * inv;
        }
        return;
    }
    int c = blockIdx.x;
    float4 wv = *reinterpret_cast<const float4*>(wd + (size_t)c*1024 + t*4);
    uint2 hi, lo; split4(wv, hi, lo);
    *reinterpret_cast<uint2*>(&d_wh[(size_t)c*1024 + t*4]) = hi;
    *reinterpret_cast<uint2*>(&d_wl[(size_t)c*1024 + t*4]) = lo;
    float4 v = reinterpret_cast<const float4*>(x + c*HWN)[t];
    float s = v.x + v.y + v.z + v.w;
    #pragma unroll
    for (int o = 16; o > 0; o >>= 1) s += __shfl_xor_sync(~0u, s, o);
    __shared__ float red[8];
    if ((t & 31) == 0) red[t >> 5] = s;
    __syncthreads();
    if (t == 0) {
        float tot = 0.f;
        #pragma unroll
        for (int w = 0; w < 8; w++) tot += red[w];
        d_mean[c] = tot * (1.f/1024.f);
    }
}

// ---- SE ----
__global__ void k_se(const float* __restrict__ w1, const float* __restrict__ w2) {
    GDC_WAIT();
    __shared__ float s[512], s1[32];
    int t = threadIdx.x;
    s[t] = d_mean[t];
    __syncthreads();
    int o = t >> 4, l = t & 15;
    float a = 0.f;
    #pragma unroll
    for (int j = 0; j < 8; j++) {
        int c = (l + j*16) * 4;
        float4 w = *reinterpret_cast<const float4*>(w1 + o*512 + c);
        a += w.x*s[c] + w.y*s[c+1] + w.z*s[c+2] + w.w*s[c+3];
    }
    #pragma unroll
    for (int off = 8; off > 0; off >>= 1) a += __shfl_down_sync(~0u, a, off, 16);
    if (l == 0) s1[o] = fmaxf(a, 0.f);
    __syncthreads();
    float b = 0.f;
    const float4* w2p = reinterpret_cast<const float4*>(w2 + t*32);
    #pragma unroll
    for (int j = 0; j < 8; j++) {
        float4 w = w2p[j];
        b += w.x*s1[j*4+0] + w.y*s1[j*4+1] + w.z*s1[j*4+2] + w.w*s1[j*4+3];
    }
    d_scale[t] = 1.f / (1.f + expf(-b));
}

// ---- scale + sigmoid + transpose ----
__global__ void k_trans(const float* __restrict__ x) {
    GDC_WAIT();
    int p0 = blockIdx.x * 32;
    int c0 = blockIdx.y * 32;
    int t = threadIdx.x;
    __shared__ float V[32][33], S[32][33];
    int r = t >> 3, q = (t & 7) * 4;
    float4 xv = *reinterpret_cast<const float4*>(x + (c0 + r)*HWN + p0 + q);
    float sc = d_scale[c0 + r];
    float4 v; v.x = xv.x*sc; v.y = xv.y*sc; v.z = xv.z*sc; v.w = xv.w*sc;
    V[r][q+0] = v.x; V[r][q+1] = v.y; V[r][q+2] = v.z; V[r][q+3] = v.w;
    S[r][q+0] = sig1(v.x);
    S[r][q+1] = sig1(v.y);
    S[r][q+2] = sig1(v.z);
    S[r][q+3] = sig1(v.w);
    __syncthreads();
    int pr = t >> 3, cq = (t & 7) * 4;
    float4 ov, sv;
    ov.x = V[cq+0][pr]; ov.y = V[cq+1][pr]; ov.z = V[cq+2][pr]; ov.w = V[cq+3][pr];
    sv.x = S[cq+0][pr]; sv.y = S[cq+1][pr]; sv.z = S[cq+2][pr]; sv.w = S[cq+3][pr];
    *reinterpret_cast<float4*>(d_out32T + (p0 + pr)*512 + c0 + cq) = ov;
    *reinterpret_cast<float4*>(d_sigT   + (p0 + pr)*512 + c0 + cq) = sv;
}

// ---- P1: blocks 0..63 gauss stage1 (256ch, 8 rows/thread); 64..191 CSA score ----
__global__ void __launch_bounds__(256) k_p1() {
    GDC_WAIT();
    __shared__ float SM[12288];   // 48KB
    int t = threadIdx.x, bid = blockIdx.x;
    if (bid < 64) {
        float* sG = SM;            // [1024]
        float* sm = SM + 1024;     // [32 x][256 c]
        #pragma unroll
        for (int j = 0; j < 4; j++) sG[t + j*256] = d_G[t + j*256];
        int c0 = (bid & 1) * 256;
        int rs = bid >> 1;   // y
        #pragma unroll
        for (int j = 0; j < 8; j++) {
            int idx = t + j*256;
            int rr = idx >> 6, cq = (idx & 63) * 4;
            *reinterpret_cast<float4*>(&sm[rr*256 + cq]) =
                *reinterpret_cast<const float4*>(d_out32T + (size_t)(rr*32 + rs)*512 + c0 + cq);
        }
        __syncthreads();
        int g = t >> 6, c4 = (t & 63) * 4;
        float4 acc[8];
        #pragma unroll
        for (int u = 0; u < 8; u++) acc[u] = make_float4(0.f, 0.f, 0.f, 0.f);
        #pragma unroll
        for (int xx = 0; xx < 32; xx += 4) {
            float4 sv0 = *reinterpret_cast<const float4*>(&sm[(xx+0)*256 + c4]);
            float4 sv1 = *reinterpret_cast<const float4*>(&sm[(xx+1)*256 + c4]);
            float4 sv2 = *reinterpret_cast<const float4*>(&sm[(xx+2)*256 + c4]);
            float4 sv3 = *reinterpret_cast<const float4*>(&sm[(xx+3)*256 + c4]);
            #pragma unroll
            for (int ii = 0; ii < 8; ii++) {
                float4 gg = *reinterpret_cast<const float4*>(&sG[(g*8+ii)*32 + xx]);
                acc[ii].x += gg.x*sv0.x + gg.y*sv1.x + gg.z*sv2.x + gg.w*sv3.x;
                acc[ii].y += gg.x*sv0.y + gg.y*sv1.y + gg.z*sv2.y + gg.w*sv3.y;
                acc[ii].z += gg.x*sv0.z + gg.y*sv1.z + gg.z*sv2.z + gg.w*sv3.z;
                acc[ii].w += gg.x*sv0.w + gg.y*sv1.w + gg.z*sv2.w + gg.w*sv3.w;
            }
        }
        #pragma unroll
        for (int ii = 0; ii < 8; ii++) {
            int i = g*8 + ii;
            *reinterpret_cast<float4*>(d_tmpT + (size_t)(i*32 + rs)*512 + c0 + c4) = acc[ii];
        }
    } else {
        int b = bid - 64, h = b >> 2, ct = b & 3;
        #pragma unroll
        for (int j = 0; j < 12; j++) {
            int idx = t + j*256;
            int r = idx >> 10, rem = idx & 1023;
            int w = rem >> 5, c4 = (rem & 31) * 4;
            int gh = h - 1 + r;
            float4 v = make_float4(0.f, 0.f, 0.f, 0.f);
            if (gh >= 0 && gh < 32)
                v = *reinterpret_cast<const float4*>(d_sigT + (size_t)(gh*32 + w)*512 + ct*128 + c4);
            *reinterpret_cast<float4*>(&SM[idx*4]) = v;   // r*4096 + w*128 + c4
        }
        __syncthreads();
        int warp = t >> 5, lane = t & 31, c4 = lane*4;
        #pragma unroll
        for (int wp = 0; wp < 4; wp++) {
            int w = wp*8 + warp;
            float4 cen = *reinterpret_cast<const float4*>(&SM[4096 + w*128 + c4]);
            float part[9];
            #pragma unroll
            for (int di = 0; di < 3; di++) {
                #pragma unroll
                for (int dj = 0; dj < 3; dj++) {
                    int d = di*3 + dj;
                    int gw = w + dj - 1;
                    int gwc = min(max(gw, 0), 31);
                    float s = (gw == gwc) ? 1.f : 0.f;
                    const float4 nb = *reinterpret_cast<const float4*>(&SM[di*4096 + gwc*128 + c4]);
                    part[d] = s * (cen.x*nb.x + cen.y*nb.y + cen.z*nb.z + cen.w*nb.w);
                }
            }
            #pragma unroll
            for (int d = 0; d < 9; d++) {
                float v = part[d];
                #pragma unroll
                for (int o = 16; o > 0; o >>= 1) v += __shfl_xor_sync(~0u, v, o);
                if (lane == 0) d_ps[ct*9216 + h*288 + w*9 + d] = v;
            }
        }
    }
}

// ---- P2: blocks 0..63 gauss stage2 (256ch, bf16 out); 64..191 CSA apply ----
__global__ void __launch_bounds__(256) k_p2() {
    GDC_WAIT();
    __shared__ float SM[12288];
    int t = threadIdx.x, bid = blockIdx.x;
    if (bid < 64) {
        float* sG = SM;
        float* sm = SM + 1024;     // [32 y][256 c]
        #pragma unroll
        for (int j = 0; j < 4; j++) sG[t + j*256] = d_G[t + j*256];
        int c0 = (bid & 1) * 256;
        int rs = bid >> 1;   // i
        #pragma unroll
        for (int j = 0; j < 8; j++) {
            int idx = t + j*256;
            int rr = idx >> 6, cq = (idx & 63) * 4;
            *reinterpret_cast<float4*>(&sm[rr*256 + cq]) =
                *reinterpret_cast<const float4*>(d_tmpT + (size_t)(rs*32 + rr)*512 + c0 + cq);
        }
        __syncthreads();
        int g = t >> 6, c4 = (t & 63) * 4;
        float4 acc[8];
        #pragma unroll
        for (int u = 0; u < 8; u++) acc[u] = make_float4(0.f, 0.f, 0.f, 0.f);
        #pragma unroll
        for (int y = 0; y < 32; y += 4) {
            float4 sv0 = *reinterpret_cast<const float4*>(&sm[(y+0)*256 + c4]);
            float4 sv1 = *reinterpret_cast<const float4*>(&sm[(y+1)*256 + c4]);
            float4 sv2 = *reinterpret_cast<const float4*>(&sm[(y+2)*256 + c4]);
            float4 sv3 = *reinterpret_cast<const float4*>(&sm[(y+3)*256 + c4]);
            #pragma unroll
            for (int ii = 0; ii < 8; ii++) {
                float4 gg = *reinterpret_cast<const float4*>(&sG[(g*8+ii)*32 + y]);
                acc[ii].x += gg.x*sv0.x + gg.y*sv1.x + gg.z*sv2.x + gg.w*sv3.x;
                acc[ii].y += gg.x*sv0.y + gg.y*sv1.y + gg.z*sv2.y + gg.w*sv3.y;
                acc[ii].z += gg.x*sv0.z + gg.y*sv1.z + gg.z*sv2.z + gg.w*sv3.z;
                acc[ii].w += gg.x*sv0.w + gg.y*sv1.w + gg.z*sv2.w + gg.w*sv3.w;
            }
        }
        #pragma unroll
        for (int ii = 0; ii < 8; ii++) {
            int k = g*8 + ii;
            size_t f = (size_t)(rs*32 + k)*512 + c0 + c4;
            uint2 hi, lo; split4(acc[ii], hi, lo);
            *reinterpret_cast<uint2*>(&d_cath[f]) = hi;
            *reinterpret_cast<uint2*>(&d_catl[f]) = lo;
        }
    } else {
        int b = bid - 64, h = b >> 2, ct = b & 3;
        int warp = t >> 5, lane = t & 31, c4 = lane*4;
        #pragma unroll
        for (int j = 0; j < 12; j++) {
            int idx = t + j*256;
            int r = idx >> 10, rem = idx & 1023;
            int w = rem >> 5, cq = (rem & 31) * 4;
            int gh = h - 1 + r;
            float4 v = make_float4(0.f, 0.f, 0.f, 0.f);
            if (gh >= 0 && gh < 32)
                v = *reinterpret_cast<const float4*>(d_out32T + (size_t)(gh*32 + w)*512 + ct*128 + cq);
            *reinterpret_cast<float4*>(&SM[idx*4]) = v;
        }
        float a[9];
        #pragma unroll
        for (int d = 0; d < 9; d++) a[d] = 0.f;
        if (lane < 4) {
            int w = lane*8 + warp;
            float s[9];
            #pragma unroll
            for (int d = 0; d < 9; d++)
                s[d] = (d_ps[0*9216 + h*288 + w*9 + d] + d_ps[1*9216 + h*288 + w*9 + d]
                      + d_ps[2*9216 + h*288 + w*9 + d] + d_ps[3*9216 + h*288 + w*9 + d])
                      * (1.f/512.f);
            float m = s[0];
            #pragma unroll
            for (int d = 1; d < 9; d++) m = fmaxf(m, s[d]);
            float ss = 0.f;
            #pragma unroll
            for (int d = 0; d < 9; d++) { a[d] = expf(s[d] - m); ss += a[d]; }
            float inv = 1.f / ss;
            #pragma unroll
            for (int d = 0; d < 9; d++) a[d] *= inv;
        }
        __syncthreads();
        #pragma unroll
        for (int wp = 0; wp < 4; wp++) {
            int w = wp*8 + warp;
            float at[9];
            #pragma unroll
            for (int d = 0; d < 9; d++) at[d] = __shfl_sync(~0u, a[d], wp);
            float4 acc = make_float4(0.f, 0.f, 0.f, 0.f);
            #pragma unroll
            for (int di = 0; di < 3; di++) {
                #pragma unroll
                for (int dj = 0; dj < 3; dj++) {
                    int gw = w + dj - 1;
                    int gwc = min(max(gw, 0), 31);
                    float s = (gw == gwc) ? 1.f : 0.f;
                    const float4 nb = *reinterpret_cast<const float4*>(&SM[di*4096 + gwc*128 + c4]);
                    float av = at[di*3 + dj] * s;
                    acc.x += av*nb.x; acc.y += av*nb.y; acc.z += av*nb.z; acc.w += av*nb.w;
                }
            }
            size_t f = (size_t)CHW + (size_t)(h*32 + w)*512 + ct*128 + c4;
            uint2 hi, lo; split4(acc, hi, lo);
            *reinterpret_cast<uint2*>(&d_cath[f]) = hi;
            *reinterpret_cast<uint2*>(&d_catl[f]) = lo;
        }
    }
}

// ==================== mma.sync bf16 GEMM with preconverted operands ====
#define SMA_PITCH 80
#define SMB_PITCH 272
#define OFF_AL 10240
#define OFF_BH 20480
#define OFF_BL 29184

#define LDM_X4(r0,r1,r2,r3,addr) \
  asm volatile("ldmatrix.sync.aligned.m8n8.x4.shared.b16 {%0,%1,%2,%3},[%4];" \
    : "=r"(r0),"=r"(r1),"=r"(r2),"=r"(r3) : "r"(addr))
#define LDM_X4T(r0,r1,r2,r3,addr) \
  asm volatile("ldmatrix.sync.aligned.m8n8.x4.trans.shared.b16 {%0,%1,%2,%3},[%4];" \
    : "=r"(r0),"=r"(r1),"=r"(r2),"=r"(r3) : "r"(addr))
#define MMA(d,a,b0,b1) \
  asm volatile("mma.sync.aligned.m16n8k16.row.col.f32.bf16.bf16.f32 " \
    "{%0,%1,%2,%3},{%4,%5,%6,%7},{%8,%9},{%0,%1,%2,%3};" \
    : "+f"(d[0]),"+f"(d[1]),"+f"(d[2]),"+f"(d[3]) \
    : "r"(a[0]),"r"(a[1]),"r"(a[2]),"r"(a[3]),"r"(b0),"r"(b1))

__device__ __forceinline__ uint32_t smem_u32(const void* p) {
    uint32_t a;
    asm("{ .reg .u64 t; cvta.to.shared.u64 t, %1; cvt.u32.u64 %0, t; }" : "=r"(a) : "l"(p));
    return a;
}

__global__ void __launch_bounds__(256) k_gemm_mma() {
    GDC_WAIT();
    __shared__ __align__(16) char sm[37888];
    uint32_t sb = smem_u32(sm);
    int t = threadIdx.x, wid = t >> 5, lane = t & 31;
    int n0 = blockIdx.x * 128;
    int m0 = blockIdx.y * 128;
    int kz = blockIdx.z * 256;
    int wm = (wid & 1) * 64, wn = (wid >> 1) * 32;

    float acc[4][4][4];
    #pragma unroll
    for (int a = 0; a < 4; a++)
        #pragma unroll
        for (int b = 0; b < 4; b++)
            #pragma unroll
            for (int cxx = 0; cxx < 4; cxx++) acc[a][b][cxx] = 0.f;

    int q = lane >> 3, r = lane & 7;
    uint32_t a_lm = sb + (uint32_t)(wm + r + ((q & 1) << 3)) * SMA_PITCH + ((q >> 1) << 3) * 2;
    uint32_t b_lm = sb + OFF_BH + (uint32_t)(r + ((q & 1) << 3)) * SMB_PITCH
                  + (uint32_t)(wn + ((q >> 1) << 3)) * 2;

    int am = t >> 1, half = t & 1;
    int bk = t >> 3, bq = t & 7;
    const __nv_bfloat16* agh = d_wh + (size_t)(m0 + am)*1024 + kz + half*16;
    const __nv_bfloat16* agl = d_wl + (size_t)(m0 + am)*1024 + kz + half*16;
    const __nv_bfloat16* bgh = d_cath + (size_t)(kz + bk)*1024 + n0 + bq*16;
    const __nv_bfloat16* bgl = d_catl + (size_t)(kz + bk)*1024 + n0 + bq*16;
    char* smaA = sm + am*SMA_PITCH + half*32;
    char* smbB = sm + OFF_BH + bk*SMB_PITCH + bq*32;

    for (int kc = 0; kc < 8; kc++) {
        uint4 pah0 = *reinterpret_cast<const uint4*>(agh + kc*32);
        uint4 pah1 = *reinterpret_cast<const uint4*>(agh + kc*32 + 8);
        uint4 pal0 = *reinterpret_cast<const uint4*>(agl + kc*32);
        uint4 pal1 = *reinterpret_cast<const uint4*>(agl + kc*32 + 8);
        uint4 pbh0 = *reinterpret_cast<const uint4*>(bgh + (size_t)kc*32*1024);
        uint4 pbh1 = *reinterpret_cast<const uint4*>(bgh + (size_t)kc*32*1024 + 8);
        uint4 pbl0 = *reinterpret_cast<const uint4*>(bgl + (size_t)kc*32*1024);
        uint4 pbl1 = *reinterpret_cast<const uint4*>(bgl + (size_t)kc*32*1024 + 8);
        __syncthreads();
        *reinterpret_cast<uint4*>(smaA) = pah0;
        *reinterpret_cast<uint4*>(smaA + 16) = pah1;
        *reinterpret_cast<uint4*>(smaA + OFF_AL) = pal0;
        *reinterpret_cast<uint4*>(smaA + OFF_AL + 16) = pal1;
        *reinterpret_cast<uint4*>(smbB) = pbh0;
        *reinterpret_cast<uint4*>(smbB + 16) = pbh1;
        *reinterpret_cast<uint4*>(smbB + (OFF_BL - OFF_BH)) = pbl0;
        *reinterpret_cast<uint4*>(smbB + (OFF_BL - OFF_BH) + 16) = pbl1;
        __syncthreads();
        #pragma unroll
        for (int ks = 0; ks < 2; ks++) {
            uint32_t ah[4][4], al[4][4], bh[2][4], bl[2][4];
            #pragma unroll
            for (int mi = 0; mi < 4; mi++) {
                uint32_t ad = a_lm + mi*16*SMA_PITCH + ks*32;
                LDM_X4(ah[mi][0], ah[mi][1], ah[mi][2], ah[mi][3], ad);
                LDM_X4(al[mi][0], al[mi][1], al[mi][2], al[mi][3], ad + OFF_AL);
            }
            #pragma unroll
            for (int nj = 0; nj < 2; nj++) {
                uint32_t bd = b_lm + nj*32 + ks*16*SMB_PITCH;
                LDM_X4T(bh[nj][0], bh[nj][1], bh[nj][2], bh[nj][3], bd);
                LDM_X4T(bl[nj][0], bl[nj][1], bl[nj][2], bl[nj][3], bd + (OFF_BL - OFF_BH));
            }
            #pragma unroll
            for (int mi = 0; mi < 4; mi++) {
                #pragma unroll
                for (int nj = 0; nj < 2; nj++) {
                    MMA(acc[mi][2*nj],   ah[mi], bh[nj][0], bh[nj][1]);
                    MMA(acc[mi][2*nj],   ah[mi], bl[nj][0], bl[nj][1]);
                    MMA(acc[mi][2*nj],   al[mi], bh[nj][0], bh[nj][1]);
                    MMA(acc[mi][2*nj+1], ah[mi], bh[nj][2], bh[nj][3]);
                    MMA(acc[mi][2*nj+1], ah[mi], bl[nj][2], bl[nj][3]);
                    MMA(acc[mi][2*nj+1], al[mi], bh[nj][2], bh[nj][3]);
                }
            }
        }
    }
    int g = lane >> 2, tq = lane & 3;
    float* base = d_y + (size_t)blockIdx.z * CHW;
    #pragma unroll
    for (int mi = 0; mi < 4; mi++) {
        int row = m0 + wm + mi*16 + g;
        #pragma unroll
        for (int ni = 0; ni < 4; ni++) {
            int col = n0 + wn + ni*8 + tq*2;
            *reinterpret_cast<float2*>(base + (size_t)row*1024 + col) =
                make_float2(acc[mi][ni][0], acc[mi][ni][1]);
            *reinterpret_cast<float2*>(base + (size_t)(row+8)*1024 + col) =
                make_float2(acc[mi][ni][2], acc[mi][ni][3]);
        }
    }
}

// ---- instance norm (+ k-split reduce) + leaky relu(0.2) ----
__global__ void k_inorm(float* __restrict__ out) {
    GDC_WAIT();
    int o = blockIdx.x, t = threadIdx.x;
    __shared__ float red[8];
    __shared__ float bmu, brs;
    float4 v0 = reinterpret_cast<const float4*>(d_y + 0*CHW + o*1024)[t];
    float4 v1 = reinterpret_cast<const float4*>(d_y + 1*CHW + o*1024)[t];
    float4 v2 = reinterpret_cast<const float4*>(d_y + 2*CHW + o*1024)[t];
    float4 v3 = reinterpret_cast<const float4*>(d_y + 3*CHW + o*1024)[t];
    float4 v;
    v.x = (v0.x + v1.x) + (v2.x + v3.x);
    v.y = (v0.y + v1.y) + (v2.y + v3.y);
    v.z = (v0.z + v1.z) + (v2.z + v3.z);
    v.w = (v0.w + v1.w) + (v2.w + v3.w);
    float s = v.x + v.y + v.z + v.w;
    #pragma unroll
    for (int off = 16; off > 0; off >>= 1) s += __shfl_xor_sync(~0u, s, off);
    if ((t & 31) == 0) red[t >> 5] = s;
    __syncthreads();
    if (t == 0) {
        float tot = 0.f;
        #pragma unroll
        for (int w = 0; w < 8; w++) tot += red[w];
        bmu = tot * (1.f/1024.f);
    }
    __syncthreads();
    float mu = bmu;
    float dx = v.x - mu, dy = v.y - mu, dz = v.z - mu, dw = v.w - mu;
    float qq = dx*dx + dy*dy + dz*dz + dw*dw;
    #pragma unroll
    for (int off = 16; off > 0; off >>= 1) qq += __shfl_xor_sync(~0u, qq, off);
    if ((t & 31) == 0) red[t >> 5] = qq;
    __syncthreads();
    if (t == 0) {
        float tot = 0.f;
        #pragma unroll
        for (int w = 0; w < 8; w++) tot += red[w];
        brs = rsqrtf(tot * (1.f/1024.f) + 1e-5f);
    }
    __syncthreads();
    float rs = brs;
    float4 rr;
    rr.x = dx*rs; rr.y = dy*rs; rr.z = dz*rs; rr.w = dw*rs;
    rr.x = rr.x >= 0.f ? rr.x : 0.2f*rr.x;
    rr.y = rr.y >= 0.f ? rr.y : 0.2f*rr.y;
    rr.z = rr.z >= 0.f ? rr.z : 0.2f*rr.z;
    rr.w = rr.w >= 0.f ? rr.w : 0.2f*rr.w;
    reinterpret_cast<float4*>(out + o*1024)[t] = rr;
}

// ---- PDL launch helper ----
static void launch_pdl(const void* func, dim3 grid, dim3 block, void** args, bool pdl) {
    cudaLaunchConfig_t cfg = {};
    cfg.gridDim = grid;
    cfg.blockDim = block;
    cfg.dynamicSmemBytes = 0;
    cfg.stream = 0;
    cudaLaunchAttribute attr[1];
    if (pdl) {
        attr[0].id = cudaLaunchAttributeProgrammaticStreamSerialization;
        attr[0].val.programmaticStreamSerializationAllowed = 1;
        cfg.attrs = attr;
        cfg.numAttrs = 1;
    }
    cudaLaunchKernelExC(&cfg, func, args);
}

extern "C" void kernel_launch(void* const* d_in, const int* in_sizes, int n_in,
                              void* d_out, int out_size) {
    const float* x  = (const float*)d_in[0];
    const float* w1 = (const float*)d_in[1];
    const float* w2 = (const float*)d_in[2];
    const float* wd = (const float*)d_in[3];
    float* out = (float*)d_out;

    void* a_init[]  = {(void*)&x, (void*)&wd};
    void* a_se[]    = {(void*)&w1, (void*)&w2};
    void* a_trans[] = {(void*)&x};
    void* a_out[]   = {(void*)&out};

    launch_pdl((const void*)k_init,     dim3(513),    dim3(256), a_init,  false);
    launch_pdl((const void*)k_se,       dim3(1),      dim3(512), a_se,    true);
    launch_pdl((const void*)k_trans,    dim3(32, 16), dim3(256), a_trans, true);
    launch_pdl((const void*)k_p1,       dim3(192),    dim3(256), nullptr, true);
    launch_pdl((const void*)k_p2,       dim3(192),    dim3(256), nullptr, true);
    launch_pdl((const void*)k_gemm_mma, dim3(8, 4, 4), dim3(256), nullptr, true);
    launch_pdl((const void*)k_inorm,    dim3(512),    dim3(256), a_out,   true);
}